// round 8
// baseline (speedup 1.0000x reference)
#include <cuda_runtime.h>
#include <cuda_fp16.h>
#include <math.h>

typedef unsigned long long ull;

#define NN   100000
#define EE   1600000
#define INC  128
#define HID  64
#define NCLS 40

#define SCAN_B 512
#define NB_SCAN ((NN + SCAN_B - 1) / SCAN_B)   // 196

// ---------------- device scratch ----------------
__device__ int      g_is64;
__device__ int      g_deg[NN];
__device__ float    g_dis[NN];
__device__ int      g_off[NN + 1];
__device__ int      g_pos[NN];
__device__ int      g_srcs[EE];
__device__ unsigned g_pub[NB_SCAN];
__device__ __half   g_hh[(size_t)NN * HID];    // fp16 dis-scaled x@W1
__device__ float    g_h2[(size_t)NN * HID];    // relu(agg1 + b1), fp32
__device__ __half   g_gh[(size_t)NN * NCLS];   // fp16 dis-scaled h2@W2

// ---------------- f32x2 helpers ----------------
__device__ __forceinline__ ull splat2(float a) {
    ull r; asm("mov.b64 %0, {%1, %1};" : "=l"(r) : "f"(a)); return r;
}
__device__ __forceinline__ ull fma2(ull a, ull b, ull c) {
    asm("fma.rn.f32x2 %0, %1, %2, %0;" : "+l"(c) : "l"(a), "l"(b)); return c;
}
__device__ __forceinline__ float2 up2(ull v) {
    float2 f; asm("mov.b64 {%0, %1}, %2;" : "=f"(f.x), "=f"(f.y) : "l"(v)); return f;
}

// ---------------- init: zero deg, reset scan state, dtype probe ----------------
__global__ void k_init(const int* __restrict__ e32) {
    int i = blockIdx.x * blockDim.x + threadIdx.x;
    if (i < NN) g_deg[i] = 0;
    if (i < NB_SCAN) g_pub[i] = 0u;
    if (i == 0) {
        int all0 = 1;
        for (int j = 0; j < 64; j++)
            if (e32[2 * j + 1] != 0) { all0 = 0; break; }
        g_is64 = all0;
    }
}

// ---------------- count: 8 edges per thread ----------------
__global__ void k_count(const void* __restrict__ eidx) {
    int t = blockIdx.x * blockDim.x + threadIdx.x;
    if (t >= EE / 8) return;
    int d[8];
    if (g_is64) {
        const longlong2* p = (const longlong2*)eidx + (size_t)EE / 2 + (size_t)t * 4;
        #pragma unroll
        for (int j = 0; j < 4; j++) {
            longlong2 a = p[j];
            d[2 * j] = (int)a.x; d[2 * j + 1] = (int)a.y;
        }
    } else {
        const int4* p = (const int4*)eidx + (size_t)EE / 4 + (size_t)t * 2;
        int4 a = p[0], b = p[1];
        d[0] = a.x; d[1] = a.y; d[2] = a.z; d[3] = a.w;
        d[4] = b.x; d[5] = b.y; d[6] = b.z; d[7] = b.w;
    }
    #pragma unroll
    for (int j = 0; j < 8; j++)
        if ((unsigned)d[j] < NN) atomicAdd(&g_deg[d[j]], 1);
}

// ---------------- single-pass scan with decoupled lookback ----------------
__global__ __launch_bounds__(SCAN_B) void k_scan() {
    __shared__ int s[SCAN_B];
    int tid = threadIdx.x;
    int b = blockIdx.x;
    int i = b * SCAN_B + tid;
    int v = (i < NN) ? g_deg[i] : 0;
    s[tid] = v;
    __syncthreads();
    for (int o = 1; o < SCAN_B; o <<= 1) {
        int t = 0;
        if (tid >= o) t = s[tid - o];
        __syncthreads();
        s[tid] += t;
        __syncthreads();
    }
    int incl = s[tid];

    if (tid == SCAN_B - 1)
        atomicExch(&g_pub[b], 0x80000000u | (unsigned)incl);

    int pre = 0;
    if (tid < b) {
        unsigned u;
        do { u = atomicAdd(&g_pub[tid], 0u); } while (!(u & 0x80000000u));
        pre = (int)(u & 0x7fffffffu);
    }
    __syncthreads();
    s[tid] = pre;
    __syncthreads();
    #pragma unroll
    for (int o = SCAN_B / 2; o > 0; o >>= 1) {
        if (tid < o) s[tid] += s[tid + o];
        __syncthreads();
    }
    int blockoff = s[0];

    if (i < NN) {
        int o = blockoff + incl - v;
        g_off[i] = o;
        g_pos[i] = o;
        g_dis[i] = rsqrtf((float)(v + 1));
    }
    if (b == 0 && tid == 0) g_off[NN] = EE;
}

// ---------------- fill: 8 edges per thread ----------------
__global__ void k_fill(const void* __restrict__ eidx) {
    int t = blockIdx.x * blockDim.x + threadIdx.x;
    if (t >= EE / 8) return;
    int sv[8], dv[8];
    if (g_is64) {
        const longlong2* ps = (const longlong2*)eidx + (size_t)t * 4;
        const longlong2* pd = (const longlong2*)eidx + (size_t)EE / 2 + (size_t)t * 4;
        #pragma unroll
        for (int j = 0; j < 4; j++) {
            longlong2 a = ps[j], c = pd[j];
            sv[2 * j] = (int)a.x; sv[2 * j + 1] = (int)a.y;
            dv[2 * j] = (int)c.x; dv[2 * j + 1] = (int)c.y;
        }
    } else {
        const int4* ps = (const int4*)eidx + (size_t)t * 2;
        const int4* pd = (const int4*)eidx + (size_t)EE / 4 + (size_t)t * 2;
        int4 a = ps[0], b = ps[1], c = pd[0], d = pd[1];
        sv[0] = a.x; sv[1] = a.y; sv[2] = a.z; sv[3] = a.w;
        sv[4] = b.x; sv[5] = b.y; sv[6] = b.z; sv[7] = b.w;
        dv[0] = c.x; dv[1] = c.y; dv[2] = c.z; dv[3] = c.w;
        dv[4] = d.x; dv[5] = d.y; dv[6] = d.z; dv[7] = d.w;
    }
    int p[8];
    #pragma unroll
    for (int j = 0; j < 8; j++) {
        p[j] = -1;
        if ((unsigned)dv[j] < NN && (unsigned)sv[j] < NN)
            p[j] = atomicAdd(&g_pos[dv[j]], 1);
    }
    #pragma unroll
    for (int j = 0; j < 8; j++)
        if ((unsigned)p[j] < EE) g_srcs[p[j]] = sv[j];
}

// ---------------- GEMM1: g_hh = fp16(dis * (x @ W1)), TM=4 TN=8, prefetched ----------------
// block = 256 threads = 32 rowg (4 rows) x 8 colg (8 cols); tile 128x64
// Depends only on g_deg (computes dis inline), NOT on k_scan.
__global__ __launch_bounds__(256) void k_gemm1(const float* __restrict__ x,
                                               const float* __restrict__ W1) {
    __shared__ ull ws[INC * 32];          // [128 k][32 ull] = 64 cols, 32 KB
    int tid = threadIdx.x;
    {
        const ulonglong2* w16 = (const ulonglong2*)W1;
        ulonglong2* wd = (ulonglong2*)ws;
        #pragma unroll
        for (int j = tid; j < INC * HID / 4; j += 256) wd[j] = w16[j];
    }
    __syncthreads();

    int colg = tid & 7;
    int rowg = tid >> 3;                  // 0..31
    int row0 = blockIdx.x * 128 + rowg * 4;

    bool ok[4];
    const float4* xr[4];
    #pragma unroll
    for (int i = 0; i < 4; i++) {
        ok[i] = (row0 + i) < NN;
        xr[i] = (const float4*)(x + (size_t)(ok[i] ? row0 + i : 0) * INC);
    }

    ull acc[4][4];
    #pragma unroll
    for (int i = 0; i < 4; i++)
        #pragma unroll
        for (int j = 0; j < 4; j++) acc[i][j] = 0ULL;

    const ulonglong2* wsv = (const ulonglong2*)ws;

    float4 cur[4], nxt[4];
    #pragma unroll
    for (int i = 0; i < 4; i++) cur[i] = xr[i][0];

    #pragma unroll 1
    for (int kc = 0; kc < 32; kc++) {
        if (kc < 31) {
            #pragma unroll
            for (int i = 0; i < 4; i++) nxt[i] = xr[i][kc + 1];   // prefetch
        }
        #pragma unroll
        for (int kk = 0; kk < 4; kk++) {
            int k = kc * 4 + kk;
            ulonglong2 b01 = wsv[k * 16 + colg * 2];
            ulonglong2 b23 = wsv[k * 16 + colg * 2 + 1];
            #pragma unroll
            for (int i = 0; i < 4; i++) {
                ull as = splat2(((const float*)&cur[i])[kk]);
                acc[i][0] = fma2(as, b01.x, acc[i][0]);
                acc[i][1] = fma2(as, b01.y, acc[i][1]);
                acc[i][2] = fma2(as, b23.x, acc[i][2]);
                acc[i][3] = fma2(as, b23.y, acc[i][3]);
            }
        }
        #pragma unroll
        for (int i = 0; i < 4; i++) cur[i] = nxt[i];
    }

    #pragma unroll
    for (int i = 0; i < 4; i++) {
        if (!ok[i]) continue;
        float di = rsqrtf((float)(g_deg[row0 + i] + 1));   // dis from deg (no scan dep)
        uint4 o;
        float2 f; __half2 h;
        f = up2(acc[i][0]); h = __floats2half2_rn(f.x * di, f.y * di); o.x = *(unsigned*)&h;
        f = up2(acc[i][1]); h = __floats2half2_rn(f.x * di, f.y * di); o.y = *(unsigned*)&h;
        f = up2(acc[i][2]); h = __floats2half2_rn(f.x * di, f.y * di); o.z = *(unsigned*)&h;
        f = up2(acc[i][3]); h = __floats2half2_rn(f.x * di, f.y * di); o.w = *(unsigned*)&h;
        *(uint4*)(g_hh + (size_t)(row0 + i) * HID + colg * 8) = o;
    }
}

// ---------------- Agg1: 4 edge-groups/warp, 2-deep pipelined gathers ----------------
__global__ __launch_bounds__(256) void k_agg1(const float* __restrict__ b1) {
    int gwarp = (blockIdx.x * blockDim.x + threadIdx.x) >> 5;
    if (gwarp >= NN) return;
    int node = gwarp;
    int lane = threadIdx.x & 31;
    int grp = lane >> 3;
    int l8  = lane & 7;

    const uint4* hh = (const uint4*)g_hh;
    float acc[8];
    #pragma unroll
    for (int j = 0; j < 8; j++) acc[j] = 0.f;

    if (grp == 0) {                    // self term (prescaled)
        uint4 v = hh[(size_t)node * 8 + l8];
        float2 f;
        f = __half22float2(*(__half2*)&v.x); acc[0] = f.x; acc[1] = f.y;
        f = __half22float2(*(__half2*)&v.y); acc[2] = f.x; acc[3] = f.y;
        f = __half22float2(*(__half2*)&v.z); acc[4] = f.x; acc[5] = f.y;
        f = __half22float2(*(__half2*)&v.w); acc[6] = f.x; acc[7] = f.y;
    }

    int beg = g_off[node], end = g_off[node + 1];
    int e = beg + grp;
    bool hA = e < end;
    bool hB = e + 4 < end;
    int sA = hA ? g_srcs[e] : 0;
    int sB = hB ? g_srcs[e + 4] : 0;

    while (hA) {
        int en = e + 8;
        bool hA2 = en < end, hB2 = en + 4 < end;
        int sA2 = hA2 ? g_srcs[en] : 0;
        int sB2 = hB2 ? g_srcs[en + 4] : 0;

        uint4 vA = hh[(size_t)sA * 8 + l8];
        uint4 vB = hB ? hh[(size_t)sB * 8 + l8] : make_uint4(0u, 0u, 0u, 0u);

        float2 f;
        f = __half22float2(*(__half2*)&vA.x); acc[0] += f.x; acc[1] += f.y;
        f = __half22float2(*(__half2*)&vA.y); acc[2] += f.x; acc[3] += f.y;
        f = __half22float2(*(__half2*)&vA.z); acc[4] += f.x; acc[5] += f.y;
        f = __half22float2(*(__half2*)&vA.w); acc[6] += f.x; acc[7] += f.y;
        f = __half22float2(*(__half2*)&vB.x); acc[0] += f.x; acc[1] += f.y;
        f = __half22float2(*(__half2*)&vB.y); acc[2] += f.x; acc[3] += f.y;
        f = __half22float2(*(__half2*)&vB.z); acc[4] += f.x; acc[5] += f.y;
        f = __half22float2(*(__half2*)&vB.w); acc[6] += f.x; acc[7] += f.y;

        hA = hA2; hB = hB2; sA = sA2; sB = sB2; e = en;
    }

    #pragma unroll
    for (int j = 0; j < 8; j++)
        acc[j] += __shfl_down_sync(0xffffffffu, acc[j], 16);
    #pragma unroll
    for (int j = 0; j < 8; j++)
        acc[j] += __shfl_down_sync(0xffffffffu, acc[j], 8);

    if (grp == 0) {
        float di = g_dis[node];
        float4 b0 = ((const float4*)b1)[l8 * 2];
        float4 b4 = ((const float4*)b1)[l8 * 2 + 1];
        float4* o = (float4*)(g_h2 + (size_t)node * HID + l8 * 8);
        o[0] = make_float4(fmaxf(fmaf(di, acc[0], b0.x), 0.f),
                           fmaxf(fmaf(di, acc[1], b0.y), 0.f),
                           fmaxf(fmaf(di, acc[2], b0.z), 0.f),
                           fmaxf(fmaf(di, acc[3], b0.w), 0.f));
        o[1] = make_float4(fmaxf(fmaf(di, acc[4], b4.x), 0.f),
                           fmaxf(fmaf(di, acc[5], b4.y), 0.f),
                           fmaxf(fmaf(di, acc[6], b4.z), 0.f),
                           fmaxf(fmaf(di, acc[7], b4.w), 0.f));
    }
}

// ---------------- GEMM2: g_gh = fp16(dis * (h2 @ W2)), TM=4 TN=10, prefetched ----------------
// block = 256 threads = 64 rowg (4 rows) x 4 colg (10 cols); tile 256x40
__global__ __launch_bounds__(256) void k_gemm2(const float* __restrict__ W2) {
    __shared__ ull ws[HID * 20];          // [64 k][20 ull] = 40 cols, 10 KB
    int tid = threadIdx.x;
    {
        const ulonglong2* w16 = (const ulonglong2*)W2;
        ulonglong2* wd = (ulonglong2*)ws;
        #pragma unroll
        for (int j = tid; j < HID * NCLS / 4; j += 256) wd[j] = w16[j];
    }
    __syncthreads();

    int colg = tid & 3;
    int rowg = tid >> 2;                  // 0..63
    int row0 = blockIdx.x * 256 + rowg * 4;

    bool ok[4];
    const float4* hr[4];
    #pragma unroll
    for (int i = 0; i < 4; i++) {
        ok[i] = (row0 + i) < NN;
        hr[i] = (const float4*)(g_h2 + (size_t)(ok[i] ? row0 + i : 0) * HID);
    }

    ull acc[4][5];
    #pragma unroll
    for (int i = 0; i < 4; i++)
        #pragma unroll
        for (int j = 0; j < 5; j++) acc[i][j] = 0ULL;

    float4 cur[4], nxt[4];
    #pragma unroll
    for (int i = 0; i < 4; i++) cur[i] = hr[i][0];

    #pragma unroll 1
    for (int kc = 0; kc < 16; kc++) {
        if (kc < 15) {
            #pragma unroll
            for (int i = 0; i < 4; i++) nxt[i] = hr[i][kc + 1];
        }
        #pragma unroll
        for (int kk = 0; kk < 4; kk++) {
            int k = kc * 4 + kk;
            ull b[5];
            #pragma unroll
            for (int j = 0; j < 5; j++) b[j] = ws[k * 20 + colg * 5 + j];
            #pragma unroll
            for (int i = 0; i < 4; i++) {
                ull as = splat2(((const float*)&cur[i])[kk]);
                #pragma unroll
                for (int j = 0; j < 5; j++)
                    acc[i][j] = fma2(as, b[j], acc[i][j]);
            }
        }
        #pragma unroll
        for (int i = 0; i < 4; i++) cur[i] = nxt[i];
    }

    #pragma unroll
    for (int i = 0; i < 4; i++) {
        if (!ok[i]) continue;
        float di = g_dis[row0 + i];
        unsigned* dst = (unsigned*)(g_gh + (size_t)(row0 + i) * NCLS + colg * 10);
        #pragma unroll
        for (int j = 0; j < 5; j++) {
            float2 f = up2(acc[i][j]);
            __half2 h = __floats2half2_rn(f.x * di, f.y * di);
            dst[j] = *(unsigned*)&h;
        }
    }
}

// ---------------- Agg2: 3 edge-groups/warp, 2-deep pipelined gathers ----------------
__global__ __launch_bounds__(256) void k_agg2(const float* __restrict__ b2,
                                              float* __restrict__ out) {
    int gwarp = (blockIdx.x * blockDim.x + threadIdx.x) >> 5;
    if (gwarp >= NN) return;
    int node = gwarp;
    int lane = threadIdx.x & 31;
    int grp = lane / 10;
    int li  = lane - grp * 10;

    const uint2* gg = (const uint2*)g_gh;
    float acc[4] = {0.f, 0.f, 0.f, 0.f};

    if (grp == 0) {
        uint2 v = gg[(size_t)node * 10 + li];
        float2 f;
        f = __half22float2(*(__half2*)&v.x); acc[0] = f.x; acc[1] = f.y;
        f = __half22float2(*(__half2*)&v.y); acc[2] = f.x; acc[3] = f.y;
    }

    int beg = g_off[node], end = g_off[node + 1];
    if (grp < 3) {
        int e = beg + grp;
        bool hA = e < end;
        bool hB = e + 3 < end;
        int sA = hA ? g_srcs[e] : 0;
        int sB = hB ? g_srcs[e + 3] : 0;

        while (hA) {
            int en = e + 6;
            bool hA2 = en < end, hB2 = en + 3 < end;
            int sA2 = hA2 ? g_srcs[en] : 0;
            int sB2 = hB2 ? g_srcs[en + 3] : 0;

            uint2 vA = gg[(size_t)sA * 10 + li];
            uint2 vB = hB ? gg[(size_t)sB * 10 + li] : make_uint2(0u, 0u);

            float2 f;
            f = __half22float2(*(__half2*)&vA.x); acc[0] += f.x; acc[1] += f.y;
            f = __half22float2(*(__half2*)&vA.y); acc[2] += f.x; acc[3] += f.y;
            f = __half22float2(*(__half2*)&vB.x); acc[0] += f.x; acc[1] += f.y;
            f = __half22float2(*(__half2*)&vB.y); acc[2] += f.x; acc[3] += f.y;

            hA = hA2; hB = hB2; sA = sA2; sB = sB2; e = en;
        }
    }

    #pragma unroll
    for (int j = 0; j < 4; j++) {
        float t1 = __shfl_down_sync(0xffffffffu, acc[j], 10);
        float t2 = __shfl_down_sync(0xffffffffu, acc[j], 20);
        acc[j] += t1 + t2;
    }

    if (grp == 0) {
        float di = g_dis[node];
        float4 b = ((const float4*)b2)[li];
        float4 r;
        r.x = fmaf(di, acc[0], b.x);
        r.y = fmaf(di, acc[1], b.y);
        r.z = fmaf(di, acc[2], b.z);
        r.w = fmaf(di, acc[3], b.w);
        ((float4*)out)[(size_t)node * 10 + li] = r;
    }
}

// ---------------- launch ----------------
extern "C" void kernel_launch(void* const* d_in, const int* in_sizes, int n_in,
                              void* d_out, int out_size) {
    const float* x    = (const float*)d_in[0];
    const void*  eidx = d_in[1];
    const float* W1   = (const float*)d_in[2];
    const float* b1   = (const float*)d_in[3];
    const float* W2   = (const float*)d_in[4];
    const float* b2   = (const float*)d_in[5];
    float* out = (float*)d_out;

    static cudaStream_t s2 = nullptr;
    static cudaEvent_t evD = nullptr, evG = nullptr;
    static bool use2 = false;
    if (!s2) {
        use2 = (cudaStreamCreateWithFlags(&s2, cudaStreamNonBlocking) == cudaSuccess) &&
               (cudaEventCreateWithFlags(&evD, cudaEventDisableTiming) == cudaSuccess) &&
               (cudaEventCreateWithFlags(&evG, cudaEventDisableTiming) == cudaSuccess);
        if (!use2) s2 = (cudaStream_t)0x1;
    }

    k_init<<<(NN + 255) / 256, 256>>>((const int*)eidx);
    k_count<<<(EE / 8 + 255) / 256, 256>>>(eidx);        // deg ready here

    if (use2) {
        cudaEventRecord(evD, 0);
        cudaStreamWaitEvent(s2, evD, 0);
        k_gemm1<<<(NN + 127) / 128, 256, 0, s2>>>(x, W1);   // ∥ scan+fill
        cudaEventRecord(evG, s2);

        k_scan<<<NB_SCAN, SCAN_B>>>();
        k_fill<<<(EE / 8 + 255) / 256, 256>>>(eidx);

        cudaStreamWaitEvent(0, evG, 0);
    } else {
        k_scan<<<NB_SCAN, SCAN_B>>>();
        k_gemm1<<<(NN + 127) / 128, 256>>>(x, W1);
        k_fill<<<(EE / 8 + 255) / 256, 256>>>(eidx);
    }

    k_agg1<<<NN / 8, 256>>>(b1);
    k_gemm2<<<(NN + 255) / 256, 256>>>(W2);
    k_agg2<<<NN / 8, 256>>>(b2, out);
}

// round 9
// speedup vs baseline: 1.1148x; 1.1148x over previous
#include <cuda_runtime.h>
#include <cuda_fp16.h>
#include <math.h>

typedef unsigned long long ull;

#define NN   100000
#define EE   1600000
#define INC  128
#define HID  64
#define NCLS 40

#define SCAN_B 512
#define NB_SCAN ((NN + SCAN_B - 1) / SCAN_B)   // 196

// ---------------- device scratch ----------------
__device__ int      g_is64;
__device__ int      g_deg[NN];
__device__ float    g_dis[NN];
__device__ int      g_off[NN + 1];
__device__ int      g_pos[NN];
__device__ int      g_srcs[EE];
__device__ unsigned g_pub[NB_SCAN];
__device__ __half   g_hh[(size_t)NN * HID];    // fp16 dis-scaled x@W1
__device__ float    g_h2[(size_t)NN * HID];    // relu(agg1 + b1), fp32
__device__ __half   g_gh[(size_t)NN * NCLS];   // fp16 dis-scaled h2@W2

// ---------------- f32x2 helpers ----------------
__device__ __forceinline__ ull splat2(float a) {
    ull r; asm("mov.b64 %0, {%1, %1};" : "=l"(r) : "f"(a)); return r;
}
__device__ __forceinline__ ull fma2(ull a, ull b, ull c) {
    asm("fma.rn.f32x2 %0, %1, %2, %0;" : "+l"(c) : "l"(a), "l"(b)); return c;
}
__device__ __forceinline__ float2 up2(ull v) {
    float2 f; asm("mov.b64 {%0, %1}, %2;" : "=f"(f.x), "=f"(f.y) : "l"(v)); return f;
}

// ---------------- init: zero deg, reset scan state, dtype probe ----------------
__global__ void k_init(const int* __restrict__ e32) {
    int i = blockIdx.x * blockDim.x + threadIdx.x;
    if (i < NN) g_deg[i] = 0;
    if (i < NB_SCAN) g_pub[i] = 0u;
    if (i == 0) {
        int all0 = 1;
        for (int j = 0; j < 64; j++)
            if (e32[2 * j + 1] != 0) { all0 = 0; break; }
        g_is64 = all0;
    }
}

// ---------------- count: 8 edges per thread ----------------
__global__ void k_count(const void* __restrict__ eidx) {
    int t = blockIdx.x * blockDim.x + threadIdx.x;
    if (t >= EE / 8) return;
    int d[8];
    if (g_is64) {
        const longlong2* p = (const longlong2*)eidx + (size_t)EE / 2 + (size_t)t * 4;
        #pragma unroll
        for (int j = 0; j < 4; j++) {
            longlong2 a = p[j];
            d[2 * j] = (int)a.x; d[2 * j + 1] = (int)a.y;
        }
    } else {
        const int4* p = (const int4*)eidx + (size_t)EE / 4 + (size_t)t * 2;
        int4 a = p[0], b = p[1];
        d[0] = a.x; d[1] = a.y; d[2] = a.z; d[3] = a.w;
        d[4] = b.x; d[5] = b.y; d[6] = b.z; d[7] = b.w;
    }
    #pragma unroll
    for (int j = 0; j < 8; j++)
        if ((unsigned)d[j] < NN) atomicAdd(&g_deg[d[j]], 1);
}

// ---------------- single-pass scan with decoupled lookback ----------------
__global__ __launch_bounds__(SCAN_B) void k_scan() {
    __shared__ int s[SCAN_B];
    int tid = threadIdx.x;
    int b = blockIdx.x;
    int i = b * SCAN_B + tid;
    int v = (i < NN) ? g_deg[i] : 0;
    s[tid] = v;
    __syncthreads();
    for (int o = 1; o < SCAN_B; o <<= 1) {
        int t = 0;
        if (tid >= o) t = s[tid - o];
        __syncthreads();
        s[tid] += t;
        __syncthreads();
    }
    int incl = s[tid];

    if (tid == SCAN_B - 1)
        atomicExch(&g_pub[b], 0x80000000u | (unsigned)incl);

    int pre = 0;
    if (tid < b) {
        unsigned u;
        do { u = atomicAdd(&g_pub[tid], 0u); } while (!(u & 0x80000000u));
        pre = (int)(u & 0x7fffffffu);
    }
    __syncthreads();
    s[tid] = pre;
    __syncthreads();
    #pragma unroll
    for (int o = SCAN_B / 2; o > 0; o >>= 1) {
        if (tid < o) s[tid] += s[tid + o];
        __syncthreads();
    }
    int blockoff = s[0];

    if (i < NN) {
        int o = blockoff + incl - v;
        g_off[i] = o;
        g_pos[i] = o;
        g_dis[i] = rsqrtf((float)(v + 1));
    }
    if (b == 0 && tid == 0) g_off[NN] = EE;
}

// ---------------- fill: 8 edges per thread ----------------
__global__ void k_fill(const void* __restrict__ eidx) {
    int t = blockIdx.x * blockDim.x + threadIdx.x;
    if (t >= EE / 8) return;
    int sv[8], dv[8];
    if (g_is64) {
        const longlong2* ps = (const longlong2*)eidx + (size_t)t * 4;
        const longlong2* pd = (const longlong2*)eidx + (size_t)EE / 2 + (size_t)t * 4;
        #pragma unroll
        for (int j = 0; j < 4; j++) {
            longlong2 a = ps[j], c = pd[j];
            sv[2 * j] = (int)a.x; sv[2 * j + 1] = (int)a.y;
            dv[2 * j] = (int)c.x; dv[2 * j + 1] = (int)c.y;
        }
    } else {
        const int4* ps = (const int4*)eidx + (size_t)t * 2;
        const int4* pd = (const int4*)eidx + (size_t)EE / 4 + (size_t)t * 2;
        int4 a = ps[0], b = ps[1], c = pd[0], d = pd[1];
        sv[0] = a.x; sv[1] = a.y; sv[2] = a.z; sv[3] = a.w;
        sv[4] = b.x; sv[5] = b.y; sv[6] = b.z; sv[7] = b.w;
        dv[0] = c.x; dv[1] = c.y; dv[2] = c.z; dv[3] = c.w;
        dv[4] = d.x; dv[5] = d.y; dv[6] = d.z; dv[7] = d.w;
    }
    int p[8];
    #pragma unroll
    for (int j = 0; j < 8; j++) {
        p[j] = -1;
        if ((unsigned)dv[j] < NN && (unsigned)sv[j] < NN)
            p[j] = atomicAdd(&g_pos[dv[j]], 1);
    }
    #pragma unroll
    for (int j = 0; j < 8; j++)
        if ((unsigned)p[j] < EE) g_srcs[p[j]] = sv[j];
}

// ---------------- GEMM1: g_hh = fp16(dis * (x @ W1)), 8x8 register tile (R7) ----------------
// block = 128 threads = 16 rowg (8 rows) x 8 colg (8 cols); tile 128x64
// dis computed from g_deg (no scan dependency).
__global__ __launch_bounds__(128) void k_gemm1(const float* __restrict__ x,
                                               const float* __restrict__ W1) {
    __shared__ ull ws[INC * 32];          // 32 KB
    int tid = threadIdx.x;
    {
        const ulonglong2* w16 = (const ulonglong2*)W1;
        ulonglong2* wd = (ulonglong2*)ws;
        #pragma unroll
        for (int j = tid; j < INC * HID / 4; j += 128) wd[j] = w16[j];
    }
    __syncthreads();

    int colg = tid & 7;
    int rowg = tid >> 3;
    int row0 = blockIdx.x * 128 + rowg * 8;

    bool ok[8];
    const float4* xr[8];
    #pragma unroll
    for (int i = 0; i < 8; i++) {
        ok[i] = (row0 + i) < NN;
        xr[i] = (const float4*)(x + (size_t)(ok[i] ? row0 + i : 0) * INC);
    }

    ull acc[8][4];
    #pragma unroll
    for (int i = 0; i < 8; i++)
        #pragma unroll
        for (int j = 0; j < 4; j++) acc[i][j] = 0ULL;

    const ulonglong2* wsv = (const ulonglong2*)ws;
    #pragma unroll 2
    for (int kc = 0; kc < 32; kc++) {
        float4 a4[8];
        #pragma unroll
        for (int i = 0; i < 8; i++) a4[i] = xr[i][kc];
        #pragma unroll
        for (int kk = 0; kk < 4; kk++) {
            int k = kc * 4 + kk;
            ulonglong2 b01 = wsv[k * 16 + colg * 2];
            ulonglong2 b23 = wsv[k * 16 + colg * 2 + 1];
            #pragma unroll
            for (int i = 0; i < 8; i++) {
                ull as = splat2(((const float*)&a4[i])[kk]);
                acc[i][0] = fma2(as, b01.x, acc[i][0]);
                acc[i][1] = fma2(as, b01.y, acc[i][1]);
                acc[i][2] = fma2(as, b23.x, acc[i][2]);
                acc[i][3] = fma2(as, b23.y, acc[i][3]);
            }
        }
    }

    #pragma unroll
    for (int i = 0; i < 8; i++) {
        if (!ok[i]) continue;
        float di = rsqrtf((float)(g_deg[row0 + i] + 1));
        uint4 o;
        float2 f; __half2 h;
        f = up2(acc[i][0]); h = __floats2half2_rn(f.x * di, f.y * di); o.x = *(unsigned*)&h;
        f = up2(acc[i][1]); h = __floats2half2_rn(f.x * di, f.y * di); o.y = *(unsigned*)&h;
        f = up2(acc[i][2]); h = __floats2half2_rn(f.x * di, f.y * di); o.z = *(unsigned*)&h;
        f = up2(acc[i][3]); h = __floats2half2_rn(f.x * di, f.y * di); o.w = *(unsigned*)&h;
        *(uint4*)(g_hh + (size_t)(row0 + i) * HID + colg * 8) = o;
    }
}

// ---------------- Agg1: 4 edge-groups/warp, 3-deep pipelined gathers ----------------
__global__ __launch_bounds__(256) void k_agg1(const float* __restrict__ b1) {
    int gwarp = (blockIdx.x * blockDim.x + threadIdx.x) >> 5;
    if (gwarp >= NN) return;
    int node = gwarp;
    int lane = threadIdx.x & 31;
    int grp = lane >> 3;
    int l8  = lane & 7;

    const uint4* hh = (const uint4*)g_hh;
    float acc[8];
    #pragma unroll
    for (int j = 0; j < 8; j++) acc[j] = 0.f;

    if (grp == 0) {                    // self term (prescaled)
        uint4 v = hh[(size_t)node * 8 + l8];
        float2 f;
        f = __half22float2(*(__half2*)&v.x); acc[0] = f.x; acc[1] = f.y;
        f = __half22float2(*(__half2*)&v.y); acc[2] = f.x; acc[3] = f.y;
        f = __half22float2(*(__half2*)&v.z); acc[4] = f.x; acc[5] = f.y;
        f = __half22float2(*(__half2*)&v.w); acc[6] = f.x; acc[7] = f.y;
    }

    int beg = g_off[node], end = g_off[node + 1];
    int e = beg + grp;                 // this group's edges: e, e+4, e+8, ...
    bool hA = e < end;
    bool hB = e + 4 < end;
    bool hC = e + 8 < end;
    int sA = hA ? g_srcs[e] : 0;
    int sB = hB ? g_srcs[e + 4] : 0;
    int sC = hC ? g_srcs[e + 8] : 0;

    while (hA) {
        int en = e + 12;
        bool hA2 = en < end, hB2 = en + 4 < end, hC2 = en + 8 < end;
        int sA2 = hA2 ? g_srcs[en] : 0;
        int sB2 = hB2 ? g_srcs[en + 4] : 0;
        int sC2 = hC2 ? g_srcs[en + 8] : 0;

        // three row loads in flight (MLP=3)
        uint4 vA = hh[(size_t)sA * 8 + l8];
        uint4 vB = hB ? hh[(size_t)sB * 8 + l8] : make_uint4(0u, 0u, 0u, 0u);
        uint4 vC = hC ? hh[(size_t)sC * 8 + l8] : make_uint4(0u, 0u, 0u, 0u);

        float2 f;
        f = __half22float2(*(__half2*)&vA.x); acc[0] += f.x; acc[1] += f.y;
        f = __half22float2(*(__half2*)&vA.y); acc[2] += f.x; acc[3] += f.y;
        f = __half22float2(*(__half2*)&vA.z); acc[4] += f.x; acc[5] += f.y;
        f = __half22float2(*(__half2*)&vA.w); acc[6] += f.x; acc[7] += f.y;
        f = __half22float2(*(__half2*)&vB.x); acc[0] += f.x; acc[1] += f.y;
        f = __half22float2(*(__half2*)&vB.y); acc[2] += f.x; acc[3] += f.y;
        f = __half22float2(*(__half2*)&vB.z); acc[4] += f.x; acc[5] += f.y;
        f = __half22float2(*(__half2*)&vB.w); acc[6] += f.x; acc[7] += f.y;
        f = __half22float2(*(__half2*)&vC.x); acc[0] += f.x; acc[1] += f.y;
        f = __half22float2(*(__half2*)&vC.y); acc[2] += f.x; acc[3] += f.y;
        f = __half22float2(*(__half2*)&vC.z); acc[4] += f.x; acc[5] += f.y;
        f = __half22float2(*(__half2*)&vC.w); acc[6] += f.x; acc[7] += f.y;

        hA = hA2; hB = hB2; hC = hC2; sA = sA2; sB = sB2; sC = sC2; e = en;
    }

    #pragma unroll
    for (int j = 0; j < 8; j++)
        acc[j] += __shfl_down_sync(0xffffffffu, acc[j], 16);
    #pragma unroll
    for (int j = 0; j < 8; j++)
        acc[j] += __shfl_down_sync(0xffffffffu, acc[j], 8);

    if (grp == 0) {
        float di = g_dis[node];
        float4 b0 = ((const float4*)b1)[l8 * 2];
        float4 b4 = ((const float4*)b1)[l8 * 2 + 1];
        float4* o = (float4*)(g_h2 + (size_t)node * HID + l8 * 8);
        o[0] = make_float4(fmaxf(fmaf(di, acc[0], b0.x), 0.f),
                           fmaxf(fmaf(di, acc[1], b0.y), 0.f),
                           fmaxf(fmaf(di, acc[2], b0.z), 0.f),
                           fmaxf(fmaf(di, acc[3], b0.w), 0.f));
        o[1] = make_float4(fmaxf(fmaf(di, acc[4], b4.x), 0.f),
                           fmaxf(fmaf(di, acc[5], b4.y), 0.f),
                           fmaxf(fmaf(di, acc[6], b4.z), 0.f),
                           fmaxf(fmaf(di, acc[7], b4.w), 0.f));
    }
}

// ---------------- GEMM2: g_gh = fp16(dis * (h2 @ W2)), 8x10 register tile (R7) ----------------
// block = 128 threads = 32 rowg (8 rows) x 4 colg (10 cols); tile 256x40
__global__ __launch_bounds__(128) void k_gemm2(const float* __restrict__ W2) {
    __shared__ ull ws[HID * 20];          // 10 KB
    int tid = threadIdx.x;
    {
        const ulonglong2* w16 = (const ulonglong2*)W2;
        ulonglong2* wd = (ulonglong2*)ws;
        #pragma unroll
        for (int j = tid; j < HID * NCLS / 4; j += 128) wd[j] = w16[j];
    }
    __syncthreads();

    int colg = tid & 3;
    int rowg = tid >> 2;
    int row0 = blockIdx.x * 256 + rowg * 8;

    bool ok[8];
    const float4* hr[8];
    #pragma unroll
    for (int i = 0; i < 8; i++) {
        ok[i] = (row0 + i) < NN;
        hr[i] = (const float4*)(g_h2 + (size_t)(ok[i] ? row0 + i : 0) * HID);
    }

    ull acc[8][5];
    #pragma unroll
    for (int i = 0; i < 8; i++)
        #pragma unroll
        for (int j = 0; j < 5; j++) acc[i][j] = 0ULL;

    #pragma unroll 2
    for (int kc = 0; kc < 16; kc++) {
        float4 a4[8];
        #pragma unroll
        for (int i = 0; i < 8; i++) a4[i] = hr[i][kc];
        #pragma unroll
        for (int kk = 0; kk < 4; kk++) {
            int k = kc * 4 + kk;
            ull b[5];
            #pragma unroll
            for (int j = 0; j < 5; j++) b[j] = ws[k * 20 + colg * 5 + j];
            #pragma unroll
            for (int i = 0; i < 8; i++) {
                ull as = splat2(((const float*)&a4[i])[kk]);
                #pragma unroll
                for (int j = 0; j < 5; j++)
                    acc[i][j] = fma2(as, b[j], acc[i][j]);
            }
        }
    }

    #pragma unroll
    for (int i = 0; i < 8; i++) {
        if (!ok[i]) continue;
        float di = g_dis[row0 + i];
        unsigned* dst = (unsigned*)(g_gh + (size_t)(row0 + i) * NCLS + colg * 10);
        #pragma unroll
        for (int j = 0; j < 5; j++) {
            float2 f = up2(acc[i][j]);
            __half2 h = __floats2half2_rn(f.x * di, f.y * di);
            dst[j] = *(unsigned*)&h;
        }
    }
}

// ---------------- Agg2: 3 edge-groups/warp, 3-deep pipelined gathers ----------------
__global__ __launch_bounds__(256) void k_agg2(const float* __restrict__ b2,
                                              float* __restrict__ out) {
    int gwarp = (blockIdx.x * blockDim.x + threadIdx.x) >> 5;
    if (gwarp >= NN) return;
    int node = gwarp;
    int lane = threadIdx.x & 31;
    int grp = lane / 10;
    int li  = lane - grp * 10;

    const uint2* gg = (const uint2*)g_gh;
    float acc[4] = {0.f, 0.f, 0.f, 0.f};

    if (grp == 0) {
        uint2 v = gg[(size_t)node * 10 + li];
        float2 f;
        f = __half22float2(*(__half2*)&v.x); acc[0] = f.x; acc[1] = f.y;
        f = __half22float2(*(__half2*)&v.y); acc[2] = f.x; acc[3] = f.y;
    }

    int beg = g_off[node], end = g_off[node + 1];
    if (grp < 3) {
        int e = beg + grp;             // this group's edges: e, e+3, e+6, ...
        bool hA = e < end;
        bool hB = e + 3 < end;
        bool hC = e + 6 < end;
        int sA = hA ? g_srcs[e] : 0;
        int sB = hB ? g_srcs[e + 3] : 0;
        int sC = hC ? g_srcs[e + 6] : 0;

        while (hA) {
            int en = e + 9;
            bool hA2 = en < end, hB2 = en + 3 < end, hC2 = en + 6 < end;
            int sA2 = hA2 ? g_srcs[en] : 0;
            int sB2 = hB2 ? g_srcs[en + 3] : 0;
            int sC2 = hC2 ? g_srcs[en + 6] : 0;

            uint2 vA = gg[(size_t)sA * 10 + li];
            uint2 vB = hB ? gg[(size_t)sB * 10 + li] : make_uint2(0u, 0u);
            uint2 vC = hC ? gg[(size_t)sC * 10 + li] : make_uint2(0u, 0u);

            float2 f;
            f = __half22float2(*(__half2*)&vA.x); acc[0] += f.x; acc[1] += f.y;
            f = __half22float2(*(__half2*)&vA.y); acc[2] += f.x; acc[3] += f.y;
            f = __half22float2(*(__half2*)&vB.x); acc[0] += f.x; acc[1] += f.y;
            f = __half22float2(*(__half2*)&vB.y); acc[2] += f.x; acc[3] += f.y;
            f = __half22float2(*(__half2*)&vC.x); acc[0] += f.x; acc[1] += f.y;
            f = __half22float2(*(__half2*)&vC.y); acc[2] += f.x; acc[3] += f.y;

            hA = hA2; hB = hB2; hC = hC2; sA = sA2; sB = sB2; sC = sC2; e = en;
        }
    }

    #pragma unroll
    for (int j = 0; j < 4; j++) {
        float t1 = __shfl_down_sync(0xffffffffu, acc[j], 10);
        float t2 = __shfl_down_sync(0xffffffffu, acc[j], 20);
        acc[j] += t1 + t2;
    }

    if (grp == 0) {
        float di = g_dis[node];
        float4 b = ((const float4*)b2)[li];
        float4 r;
        r.x = fmaf(di, acc[0], b.x);
        r.y = fmaf(di, acc[1], b.y);
        r.z = fmaf(di, acc[2], b.z);
        r.w = fmaf(di, acc[3], b.w);
        ((float4*)out)[(size_t)node * 10 + li] = r;
    }
}

// ---------------- launch ----------------
extern "C" void kernel_launch(void* const* d_in, const int* in_sizes, int n_in,
                              void* d_out, int out_size) {
    const float* x    = (const float*)d_in[0];
    const void*  eidx = d_in[1];
    const float* W1   = (const float*)d_in[2];
    const float* b1   = (const float*)d_in[3];
    const float* W2   = (const float*)d_in[4];
    const float* b2   = (const float*)d_in[5];
    float* out = (float*)d_out;

    static cudaStream_t s2 = nullptr;
    static cudaEvent_t evD = nullptr, evG = nullptr;
    static bool use2 = false;
    if (!s2) {
        use2 = (cudaStreamCreateWithFlags(&s2, cudaStreamNonBlocking) == cudaSuccess) &&
               (cudaEventCreateWithFlags(&evD, cudaEventDisableTiming) == cudaSuccess) &&
               (cudaEventCreateWithFlags(&evG, cudaEventDisableTiming) == cudaSuccess);
        if (!use2) s2 = (cudaStream_t)0x1;
    }

    k_init<<<(NN + 255) / 256, 256>>>((const int*)eidx);
    k_count<<<(EE / 8 + 255) / 256, 256>>>(eidx);        // deg ready here

    if (use2) {
        cudaEventRecord(evD, 0);
        cudaStreamWaitEvent(s2, evD, 0);
        k_gemm1<<<(NN + 127) / 128, 128, 0, s2>>>(x, W1);   // ∥ scan+fill
        cudaEventRecord(evG, s2);

        k_scan<<<NB_SCAN, SCAN_B>>>();
        k_fill<<<(EE / 8 + 255) / 256, 256>>>(eidx);

        cudaStreamWaitEvent(0, evG, 0);
    } else {
        k_scan<<<NB_SCAN, SCAN_B>>>();
        k_gemm1<<<(NN + 127) / 128, 128>>>(x, W1);
        k_fill<<<(EE / 8 + 255) / 256, 256>>>(eidx);
    }

    k_agg1<<<NN / 8, 256>>>(b1);
    k_gemm2<<<(NN + 255) / 256, 128>>>(W2);
    k_agg2<<<NN / 8, 256>>>(b2, out);
}